// round 14
// baseline (speedup 1.0000x reference)
#include <cuda_runtime.h>

// CTC forward scan, linear domain, x4-factored:
//   G_j(t+1) = W_t[s_j]*G_{j-1}(t) + G_j(t),  W_t[s] = exp(x[t,s]-x[t,4])
//   fwd[j] = log(G) + e*ln2 + sum_t x4
//
// R13 = R12 frame (single warp per batch, zero barriers) + two fixes:
//  - __launch_bounds__(TPB, 1): 255-reg budget -> no local-memory spills
//    (R12 was capped at 96 regs and spilled the PB=16 ladder state).
//  - float4 pair-table (PSTR4=17, 16B-aligned rows): one LDS.128 fetches
//    the (W[a],W[b]) pair for TWO consecutive timesteps -> ladder LDS
//    instruction count halves.
// Everything else proven in R7/R12: 32 lanes x PB {8,12,16} positions by
// seqlen tier, trapezoid KB=8 with shfl halo + packed (e,ex,hasmass) int,
// same-warp W table with one __syncwarp per 32-step chunk, pow2 common-scale
// mixing (all factors <= 1: no overflow, flush-to-zero correct).

#define XCH   32
#define KB    8
#define PSTR4 17            // float4 per table row (272B): 16B aligned
#define NBAT  2
#define TPB   (32 * NBAT)

__device__ __forceinline__ float exp2i_le(int d) {
    int b = d + 127;
    b = b < 0 ? 0 : (b > 254 ? 254 : b);
    return __int_as_float(b << 23);
}

template<int PB>
__device__ __forceinline__ void scan_batch(
    const float* __restrict__ x, const int* __restrict__ seqs,
    int sl, int bb, int nt, int nb, int ns,
    float* __restrict__ out,
    float4* __restrict__ shP,    // [2][16*PSTR4]
    float*  __restrict__ gall,   // [32*PB]
    int*    __restrict__ eall)   // [32]
{
    constexpr int NU = PB + KB - 1;       // updates per step (odd)
    constexpr int NP = (NU + 1) / 2;      // pair rows (last single, padded)
    const int l    = threadIdx.x & 31;
    const int jmin = l * PB;

    // move indices: update i writes G[i+1] (position jmin+i+1-KB), uses
    // seqs[jmin+i-KB]
    int s[NU + 1];
    #pragma unroll
    for (int k = 0; k < NU; ++k) {
        int q = jmin + k - KB;
        s[k] = (q >= 0 && q < ns) ? seqs[(long long)bb * ns + q] : 0;
    }
    s[NU] = s[NU - 1];
    int pq[NP];                            // row offset in float4 units
    #pragma unroll
    for (int q = 0; q < NP; ++q)
        pq[q] = (s[2 * q] * 4 + s[2 * q + 1]) * PSTR4;

    float G[KB + PB];
    #pragma unroll
    for (int i = 0; i < KB + PB; ++i) G[i] = 0.0f;
    if (l == 0) G[KB] = 1.0f;             // position 0: fwd=0 -> G=1
    int e = 0;

    float a0 = 0.f, a1 = 0.f, a2 = 0.f, a3 = 0.f, a4 = 0.f;
    double x4s = 0.0;

    auto prefetch = [&](int c) {          // LDG only (regs), one tau per lane
        int tt = c * XCH + l;
        if (tt < nt) {
            const float* xp = x + ((long long)tt * nb + bb) * 5;
            a0 = xp[0]; a1 = xp[1]; a2 = xp[2]; a3 = xp[3]; a4 = xp[4];
        } else {
            a0 = a1 = a2 = a3 = -1e9f;    // exp -> 0: steps past nt freeze G
            a4 = 0.f;
        }
    };
    auto convert = [&](int c) {           // expf + 16 STS.64 (half-float4)
        float w[4];
        w[0] = __expf(a0 - a4); w[1] = __expf(a1 - a4);
        w[2] = __expf(a2 - a4); w[3] = __expf(a3 - a4);
        // cell for (row, tau): float4[row*PSTR4 + tau/2], half (tau&1)
        float2* base = reinterpret_cast<float2*>(
            shP + (c & 1) * (16 * PSTR4) + (l >> 1)) + (l & 1);
        #pragma unroll
        for (int aa = 0; aa < 4; ++aa)
            #pragma unroll
            for (int bq = 0; bq < 4; ++bq)
                base[(aa * 4 + bq) * (2 * PSTR4)] = make_float2(w[aa], w[bq]);
        if (c * XCH + l < nt) x4s += (double)a4;
    };

    prefetch(0); convert(0); prefetch(1);
    __syncwarp();

    const int NC = (nt + XCH - 1) / XCH;
    for (int c = 0; c < NC; ++c) {
        // hoisted per-row pointers: ladder LDS.128 get immediate offsets
        const float4* rp[NP];
        {
            const float4* cbb = shP + (c & 1) * (16 * PSTR4);
            #pragma unroll
            for (int q = 0; q < NP; ++q) rp[q] = cbb + pq[q];
        }
        #pragma unroll 1
        for (int r = 0; r < XCH / KB; ++r) {
            // ---- exchange (shfl halo, common-scale mixing) ----
            float mx = G[KB];
            #pragma unroll
            for (int i = KB + 1; i < KB + PB; ++i) mx = fmaxf(mx, G[i]);
            int ex = (__float_as_int(mx) >> 23) - 127;
            int hm = (mx > 0.0f) ? 1 : 0;
            int pack  = (e << 9) | ((ex + 128) << 1) | hm;
            int packL = __shfl_up_sync(0xffffffffu, pack, 1);
            float h[KB];
            #pragma unroll
            for (int i = 0; i < KB; ++i)       // left lane's top KB owned
                h[i] = __shfl_up_sync(0xffffffffu, G[PB + i], 1);
            int hL  = (l == 0) ? 0 : (packL & 1);
            int exL = ((packL >> 1) & 255) - 128;
            int eL  = packL >> 9;              // arithmetic shift: sign kept
            const int NEG = -(1 << 29);
            int EO = hm ? (e + ex)   : NEG;
            int EL = hL ? (eL + exL) : NEG;
            int cc = EO > EL ? EO : EL;
            if (cc == NEG) cc = 0;
            float rs = exp2i_le(e - cc);       // <= 2^-ex -> post-mix <= 2
            float rl = hL ? exp2i_le(eL - cc) : 0.0f;
            #pragma unroll
            for (int i = 0; i < KB; ++i) G[i] = h[i] * rl;
            #pragma unroll
            for (int i = KB; i < KB + PB; ++i) G[i] *= rs;
            e = cc;

            // ---- ladder: KB steps, one LDS.128 per row per 2 steps ----
            #pragma unroll
            for (int kk = 0; kk < KB / 2; ++kk) {
                float4 V[NP];
                #pragma unroll
                for (int q = 0; q < NP; ++q) V[q] = rp[q][kk];
                // step 2kk: pairs in (x,y)
                G[NU] = fmaf(V[NP - 1].x, G[NU - 1], G[NU]);
                #pragma unroll
                for (int q = NP - 2; q >= 0; --q) {
                    G[2*q + 2] = fmaf(V[q].y, G[2*q + 1], G[2*q + 2]);
                    G[2*q + 1] = fmaf(V[q].x, G[2*q],     G[2*q + 1]);
                }
                // step 2kk+1: pairs in (z,w)
                G[NU] = fmaf(V[NP - 1].z, G[NU - 1], G[NU]);
                #pragma unroll
                for (int q = NP - 2; q >= 0; --q) {
                    G[2*q + 2] = fmaf(V[q].w, G[2*q + 1], G[2*q + 2]);
                    G[2*q + 1] = fmaf(V[q].z, G[2*q],     G[2*q + 1]);
                }
            }
            #pragma unroll
            for (int q = 0; q < NP; ++q) rp[q] += KB / 2;
        }
        convert(c + 1);      // regs from prefetch(c+1)
        __syncwarp();        // cross-lane table visibility
        prefetch(c + 2);
    }

    // ---- epilogue ----
    #pragma unroll
    for (int i = 0; i < PB; ++i) gall[jmin + i] = G[KB + i];
    eall[l] = e;
    double v = x4s;
    #pragma unroll
    for (int o = 16; o; o >>= 1)
        v += __shfl_down_sync(0xffffffffu, v, o);
    __syncwarp();
    if (l == 0) {
        float  Gv = gall[sl];
        int    ev = eall[sl / PB];
        double lv = (double)logf(Gv) + (double)ev * 0.6931471805599453 + v;
        out[bb] = (float)(-lv / (double)nt);
    }
}

__global__ __launch_bounds__(TPB, 1)
void ctc_fwd(const float* __restrict__ x,
             const int*   __restrict__ seqs,
             const int*   __restrict__ seqlens,
             float*       __restrict__ out,
             int nt, int nb, int ns)
{
    __shared__ float4 shP [NBAT][2 * 16 * PSTR4];
    __shared__ float  gall[NBAT][512];
    __shared__ int    eall[NBAT][32];

    const int w  = threadIdx.x >> 5;
    const int bb = blockIdx.x * NBAT + w;
    if (bb >= nb) return;                  // warp-uniform exit
    const int sl = seqlens[bb];

    if (sl < 8 * 32)
        scan_batch<8>(x, seqs, sl, bb, nt, nb, ns, out,
                      shP[w], gall[w], eall[w]);
    else if (sl < 12 * 32)
        scan_batch<12>(x, seqs, sl, bb, nt, nb, ns, out,
                       shP[w], gall[w], eall[w]);
    else
        scan_batch<16>(x, seqs, sl, bb, nt, nb, ns, out,
                       shP[w], gall[w], eall[w]);
}

extern "C" void kernel_launch(void* const* d_in, const int* in_sizes, int n_in,
                              void* d_out, int out_size) {
    const float* x       = (const float*)d_in[0];
    const int*   seqs    = (const int*)  d_in[1];
    const int*   seqlens = (const int*)  d_in[2];
    float*       out     = (float*)d_out;

    const int nb = in_sizes[2];
    const int ns = in_sizes[1] / nb;
    const int nt = in_sizes[0] / (nb * 5);

    ctc_fwd<<<(nb + NBAT - 1) / NBAT, TPB>>>(x, seqs, seqlens, out, nt, nb, ns);
}

// round 15
// speedup vs baseline: 1.2650x; 1.2650x over previous
#include <cuda_runtime.h>

// CTC forward scan, linear domain, x4-factored:
//   G_j(t+1) = W_t[s_j]*G_{j-1}(t) + G_j(t),  W_t[s] = exp(x[t,s]-x[t,4])
//   fwd[j] = log(G) + e*ln2 + sum_t x4
//
// R14 = R12 (best: 100.3us) + __launch_bounds__(TPB, 1) ONLY.
//   R12 compiled to a 96-reg cap -> local-memory spills in the PB=16 ladder
//   (seen as ~2x issue-slot inflation + 33% L1). R13 proved the reg budget
//   lifts (120 regs) but its float4 table added LDS bank conflicts
//   (4r mod 32 non-injective) and regressed. This round keeps the proven
//   conflict-free float2 pair-table (stride 33 float2: row bank = 2r mod 32,
//   injective over 16 rows) and changes exactly one thing: the reg budget.
//
// Frame (proven R7/R12): single warp per batch, zero barriers.
//  - 32 lanes x PB {8,12,16} positions by seqlen tier; trapezoid KB=8 with
//    shfl halo + packed (e,ex,hasmass) int; same-warp W pair-table with one
//    __syncwarp per 32-step chunk; ladder LDS.64 via per-chunk hoisted row
//    pointers (immediate offsets); pow2 common-scale mixing, all factors
//    <= 1 (no overflow; flush-to-zero correct).
//  - 2 independent warps (batches) per 64-thread CTA, grid=128 -> 1 CTA/SM.

#define XCH  32
#define KB   8
#define PSTR 33
#define NBAT 2
#define TPB  (32 * NBAT)

__device__ __forceinline__ float exp2i_le(int d) {
    int b = d + 127;
    b = b < 0 ? 0 : (b > 254 ? 254 : b);
    return __int_as_float(b << 23);
}

template<int PB>
__device__ __forceinline__ void scan_batch(
    const float* __restrict__ x, const int* __restrict__ seqs,
    int sl, int bb, int nt, int nb, int ns,
    float* __restrict__ out,
    float2* __restrict__ shP,    // [2][16*PSTR]
    float*  __restrict__ gall,   // [32*PB]
    int*    __restrict__ eall)   // [32]
{
    constexpr int NU = PB + KB - 1;       // updates per step (odd)
    constexpr int NP = (NU + 1) / 2;      // pair rows (last single, padded)
    const int l    = threadIdx.x & 31;
    const int jmin = l * PB;

    // move indices: update i writes G[i+1] (position jmin+i+1-KB), uses
    // seqs[jmin+i-KB]
    int s[NU + 1];
    #pragma unroll
    for (int k = 0; k < NU; ++k) {
        int q = jmin + k - KB;
        s[k] = (q >= 0 && q < ns) ? seqs[(long long)bb * ns + q] : 0;
    }
    s[NU] = s[NU - 1];
    int pq[NP];
    #pragma unroll
    for (int q = 0; q < NP; ++q)
        pq[q] = (s[2 * q] * 4 + s[2 * q + 1]) * PSTR;

    float G[KB + PB];
    #pragma unroll
    for (int i = 0; i < KB + PB; ++i) G[i] = 0.0f;
    if (l == 0) G[KB] = 1.0f;             // position 0: fwd=0 -> G=1
    int e = 0;

    float a0 = 0.f, a1 = 0.f, a2 = 0.f, a3 = 0.f, a4 = 0.f;
    double x4s = 0.0;

    auto prefetch = [&](int c) {          // LDG only (regs), one tau per lane
        int tt = c * XCH + l;
        if (tt < nt) {
            const float* xp = x + ((long long)tt * nb + bb) * 5;
            a0 = xp[0]; a1 = xp[1]; a2 = xp[2]; a3 = xp[3]; a4 = xp[4];
        } else {
            a0 = a1 = a2 = a3 = -1e9f;    // exp -> 0: steps past nt freeze G
            a4 = 0.f;
        }
    };
    auto convert = [&](int c) {           // expf + 16 STS.64 pair rows
        float w[4];
        w[0] = __expf(a0 - a4); w[1] = __expf(a1 - a4);
        w[2] = __expf(a2 - a4); w[3] = __expf(a3 - a4);
        float2* row = shP + (c & 1) * (16 * PSTR) + l;
        #pragma unroll
        for (int aa = 0; aa < 4; ++aa)
            #pragma unroll
            for (int bq = 0; bq < 4; ++bq)
                row[(aa * 4 + bq) * PSTR] = make_float2(w[aa], w[bq]);
        if (c * XCH + l < nt) x4s += (double)a4;
    };

    prefetch(0); convert(0); prefetch(1);
    __syncwarp();

    const int NC = (nt + XCH - 1) / XCH;
    for (int c = 0; c < NC; ++c) {
        // hoist pair-row pointers: ladder LDS get immediate offsets only
        const float2* rp[NP];
        {
            const float2* cbb = shP + (c & 1) * (16 * PSTR);
            #pragma unroll
            for (int q = 0; q < NP; ++q) rp[q] = cbb + pq[q];
        }
        #pragma unroll 1
        for (int r = 0; r < XCH / KB; ++r) {
            // ---- exchange (shfl halo, common-scale mixing) ----
            float mx = G[KB];
            #pragma unroll
            for (int i = KB + 1; i < KB + PB; ++i) mx = fmaxf(mx, G[i]);
            int ex = (__float_as_int(mx) >> 23) - 127;
            int hm = (mx > 0.0f) ? 1 : 0;
            int pack  = (e << 9) | ((ex + 128) << 1) | hm;
            int packL = __shfl_up_sync(0xffffffffu, pack, 1);
            float h[KB];
            #pragma unroll
            for (int i = 0; i < KB; ++i)       // left lane's top KB owned
                h[i] = __shfl_up_sync(0xffffffffu, G[PB + i], 1);
            int hL  = (l == 0) ? 0 : (packL & 1);
            int exL = ((packL >> 1) & 255) - 128;
            int eL  = packL >> 9;              // arithmetic shift: sign kept
            const int NEG = -(1 << 29);
            int EO = hm ? (e + ex)   : NEG;
            int EL = hL ? (eL + exL) : NEG;
            int cc = EO > EL ? EO : EL;
            if (cc == NEG) cc = 0;
            float rs = exp2i_le(e - cc);       // <= 2^-ex -> post-mix <= 2
            float rl = hL ? exp2i_le(eL - cc) : 0.0f;
            #pragma unroll
            for (int i = 0; i < KB; ++i) G[i] = h[i] * rl;
            #pragma unroll
            for (int i = KB; i < KB + PB; ++i) G[i] *= rs;
            e = cc;

            // ---- ladder: KB steps, per-step loads (ptxas pipelines) ----
            #pragma unroll
            for (int k = 0; k < KB; ++k) {
                float2 W[NP];
                #pragma unroll
                for (int q = 0; q < NP; ++q) W[q] = rp[q][k];
                // in-place, strictly descending targets (pre-step reads)
                G[NU] = fmaf(W[NP - 1].x, G[NU - 1], G[NU]);
                #pragma unroll
                for (int q = NP - 2; q >= 0; --q) {
                    G[2*q + 2] = fmaf(W[q].y, G[2*q + 1], G[2*q + 2]);
                    G[2*q + 1] = fmaf(W[q].x, G[2*q],     G[2*q + 1]);
                }
            }
            #pragma unroll
            for (int q = 0; q < NP; ++q) rp[q] += KB;
        }
        convert(c + 1);      // regs from prefetch(c+1)
        __syncwarp();        // cross-lane table visibility
        prefetch(c + 2);
    }

    // ---- epilogue ----
    #pragma unroll
    for (int i = 0; i < PB; ++i) gall[jmin + i] = G[KB + i];
    eall[l] = e;
    double v = x4s;
    #pragma unroll
    for (int o = 16; o; o >>= 1)
        v += __shfl_down_sync(0xffffffffu, v, o);
    __syncwarp();
    if (l == 0) {
        float  Gv = gall[sl];
        int    ev = eall[sl / PB];
        double lv = (double)logf(Gv) + (double)ev * 0.6931471805599453 + v;
        out[bb] = (float)(-lv / (double)nt);
    }
}

__global__ __launch_bounds__(TPB, 1)
void ctc_fwd(const float* __restrict__ x,
             const int*   __restrict__ seqs,
             const int*   __restrict__ seqlens,
             float*       __restrict__ out,
             int nt, int nb, int ns)
{
    __shared__ float2 shP [NBAT][2 * 16 * PSTR];
    __shared__ float  gall[NBAT][512];
    __shared__ int    eall[NBAT][32];

    const int w  = threadIdx.x >> 5;
    const int bb = blockIdx.x * NBAT + w;
    if (bb >= nb) return;                  // warp-uniform exit
    const int sl = seqlens[bb];

    if (sl < 8 * 32)
        scan_batch<8>(x, seqs, sl, bb, nt, nb, ns, out,
                      shP[w], gall[w], eall[w]);
    else if (sl < 12 * 32)
        scan_batch<12>(x, seqs, sl, bb, nt, nb, ns, out,
                       shP[w], gall[w], eall[w]);
    else
        scan_batch<16>(x, seqs, sl, bb, nt, nb, ns, out,
                       shP[w], gall[w], eall[w]);
}

extern "C" void kernel_launch(void* const* d_in, const int* in_sizes, int n_in,
                              void* d_out, int out_size) {
    const float* x       = (const float*)d_in[0];
    const int*   seqs    = (const int*)  d_in[1];
    const int*   seqlens = (const int*)  d_in[2];
    float*       out     = (float*)d_out;

    const int nb = in_sizes[2];
    const int ns = in_sizes[1] / nb;
    const int nt = in_sizes[0] / (nb * 5);

    ctc_fwd<<<(nb + NBAT - 1) / NBAT, TPB>>>(x, seqs, seqlens, out, nt, nb, ns);
}